// round 3
// baseline (speedup 1.0000x reference)
#include <cuda_runtime.h>
#include <math.h>

#define N_ENT 30000
#define ALL_REL 221
#define D 32
#define NL 2
#define EVAL_REL 86
#define B 16
#define E_EDGES 120000
#define BD (B * D) /* 512 */

// ---------------- device scratch (no allocations allowed) ----------------
__device__ float g_hid[2][N_ENT * BD];     // ping-pong hidden states (~123 MB)
__device__ int   g_srcStamp[N_ENT];        // source-active epoch per entity
__device__ int   g_tgtStamp[N_ENT];        // target-touched epoch per entity
__device__ int   g_edgeList[E_EDGES];      // compacted active edges (per step)
__device__ int   g_tgtList[N_ENT];         // compacted touched targets (per step)
__device__ int   g_counters[8];            // [2*step]=edgeCount, [2*step+1]=tgtCount
__device__ float g_relw[NL * B * ALL_REL]; // per-layer relation attention (B x ALL_REL)
__device__ float g_tailHid[BD];            // hid[tail[b], b, :] from pass 0

// ---------------- kernels ----------------

__global__ void k_clear() {
    int i = blockIdx.x * blockDim.x + threadIdx.x;
    int stride = gridDim.x * blockDim.x;
    for (; i < N_ENT; i += stride) { g_srcStamp[i] = 0; g_tgtStamp[i] = 0; }
    if (blockIdx.x == 0 && threadIdx.x < 8) g_counters[threadIdx.x] = 0;
}

// relw[l] = sigmoid(relu(ht @ Wrel[l] + brel[l]) @ Watt[l] + batt[l]), ht = concat(emb[head], emb[tail])
__global__ void k_relw(const int* __restrict__ head, const int* __restrict__ tail,
                       const float* __restrict__ ent_emb,
                       const float* __restrict__ Wrel, const float* __restrict__ brel,
                       const float* __restrict__ Watt, const float* __restrict__ batt) {
    __shared__ float ht[B][2 * D];
    __shared__ float h5[B][5];
    int tid = threadIdx.x; // 256 threads
    for (int idx = tid; idx < B * 2 * D; idx += blockDim.x) {
        int b = idx / (2 * D), j = idx % (2 * D);
        int ent = (j < D) ? head[b] : tail[b];
        int jj = (j < D) ? j : j - D;
        ht[b][j] = ent_emb[ent * D + jj];
    }
    __syncthreads();
    for (int l = 0; l < NL; l++) {
        for (int idx = tid; idx < B * 5; idx += blockDim.x) {
            int b = idx / 5, k = idx % 5;
            float s = brel[l * 5 + k];
            for (int j = 0; j < 2 * D; j++) s += ht[b][j] * Wrel[l * (2 * D * 5) + j * 5 + k];
            h5[b][k] = fmaxf(s, 0.f);
        }
        __syncthreads();
        for (int idx = tid; idx < B * ALL_REL; idx += blockDim.x) {
            int b = idx / ALL_REL, r = idx % ALL_REL;
            float s = batt[l * ALL_REL + r];
            for (int k = 0; k < 5; k++) s += h5[b][k] * Watt[l * (5 * ALL_REL) + k * ALL_REL + r];
            g_relw[l * B * ALL_REL + b * ALL_REL + r] = 1.f / (1.f + expf(-s));
        }
        __syncthreads();
    }
}

// zero init rows fully, set diagonal init embeddings, stamp as source-active
__global__ void k_init(const int* __restrict__ idxs, const float* __restrict__ ent_emb,
                       int buf, int stampVal) {
    float* hid = g_hid[buf];
    int tid = threadIdx.x; // 512 threads
    for (int i = tid; i < B * BD; i += blockDim.x) {
        int b = i / BD, off = i % BD;
        hid[idxs[b] * BD + off] = 0.f;
    }
    __syncthreads();
    for (int i = tid; i < B * D; i += blockDim.x) {
        int b = i / D, j = i % D;
        hid[idxs[b] * BD + b * D + j] = ent_emb[idxs[b] * D + j];
    }
    if (tid < B) g_srcStamp[idxs[tid]] = stampVal;
}

// scan all edges; compact those with active sources; first-touch-zero target rows
__global__ void k_build(const int* __restrict__ eh, const int* __restrict__ et,
                        int s, int t, int step, int dstBuf) {
    int i = blockIdx.x * blockDim.x + threadIdx.x;
    if (i >= E_EDGES) return;
    int h = eh[i];
    if (g_srcStamp[h] != s) return;
    int pos = atomicAdd(&g_counters[2 * step], 1);
    g_edgeList[pos] = i;
    int tv = et[i];
    int old = atomicMax(&g_tgtStamp[tv], t);
    if (old < t) { // exactly one first-toucher per target per step
        int ti = atomicAdd(&g_counters[2 * step + 1], 1);
        g_tgtList[ti] = tv;
        float4* row = (float4*)(g_hid[dstBuf] + (long)tv * BD);
        #pragma unroll 8
        for (int j = 0; j < BD / 4; j++) row[j] = make_float4(0.f, 0.f, 0.f, 0.f);
    }
}

// one warp per active edge: dst[tv,b,j] += w * relw[b,r] * rel[r,j] * src[h,b,j]
__global__ void k_scatter(const int* __restrict__ eh, const int* __restrict__ et,
                          const int* __restrict__ er, const float* __restrict__ ew,
                          const float* __restrict__ rel_embs,
                          int l, int step, int srcBuf, int dstBuf) {
    const float* src = g_hid[srcBuf];
    float* dst = g_hid[dstBuf];
    int lane = threadIdx.x & 31;
    int warp = (blockIdx.x * blockDim.x + threadIdx.x) >> 5;
    int nwarps = (gridDim.x * blockDim.x) >> 5;
    int cnt = g_counters[2 * step];
    const float* relw = g_relw + l * B * ALL_REL;
    const float* rel = rel_embs + l * ALL_REL * D;
    for (int w = warp; w < cnt; w += nwarps) {
        int e = g_edgeList[w];
        int h = eh[e], tv = et[e], r = er[e];
        float relv = rel[r * D + lane] * ew[e];
        const float* srow = src + (long)h * BD;
        float* drow = dst + (long)tv * BD;
        #pragma unroll
        for (int b = 0; b < B; b++) {
            float rw = relw[b * ALL_REL + r];
            float v = srow[b * D + lane];
            atomicAdd(&drow[b * D + lane], rw * relv * v);
        }
    }
}

// one warp per touched entity: in-place relu(row(16x32) @ Wlin(32x32) + blin); promote to next src set
__global__ void k_linear(const float* __restrict__ Wlin, const float* __restrict__ blin,
                         int l, int step, int buf, int nextStamp) {
    __shared__ float sW[D * D];
    __shared__ float sb[D];
    __shared__ float srow[8][BD]; // 8 warps per 256-thread block
    int tid = threadIdx.x;
    for (int i = tid; i < D * D; i += blockDim.x) sW[i] = Wlin[l * D * D + i];
    if (tid < D) sb[tid] = blin[l * D + tid];
    __syncthreads();
    float* hid = g_hid[buf];
    int lane = tid & 31, win = tid >> 5;
    int warp = (blockIdx.x * blockDim.x + tid) >> 5;
    int nwarps = (gridDim.x * blockDim.x) >> 5;
    int cnt = g_counters[2 * step + 1];
    for (int w = warp; w < cnt; w += nwarps) {
        int v = g_tgtList[w];
        float* row = hid + (long)v * BD;
        for (int i = lane; i < BD; i += 32) srow[win][i] = row[i];
        __syncwarp();
        float outv[B];
        #pragma unroll
        for (int b = 0; b < B; b++) {
            float s = sb[lane];
            #pragma unroll
            for (int ji = 0; ji < D; ji++) s += srow[win][b * D + ji] * sW[ji * D + lane];
            outv[b] = fmaxf(s, 0.f);
        }
        __syncwarp();
        #pragma unroll
        for (int b = 0; b < B; b++) row[b * D + lane] = outv[b];
        if (lane == 0 && nextStamp > 0) g_srcStamp[v] = nextStamp;
    }
}

// save hid[tail[b], b, :] after pass 0 (guarded: untouched rows are exactly 0)
__global__ void k_extract_tail(const int* __restrict__ tail, int buf, int stampVal) {
    int tid = threadIdx.x; // 512 threads
    if (tid < BD) {
        int b = tid / D, j = tid % D;
        int v = tail[b];
        g_tailHid[tid] = (g_tgtStamp[v] == stampVal) ? g_hid[buf][(long)v * BD + b * D + j] : 0.f;
    }
}

// out[b,:] = concat(emb[head], emb[tail], head_hid, tail_hid) @ Wr + br
__global__ void k_final(const int* __restrict__ head, const int* __restrict__ tail,
                        const float* __restrict__ ent_emb,
                        const float* __restrict__ Wr, const float* __restrict__ br,
                        float* __restrict__ out, int buf, int stampVal) {
    __shared__ float conc[B][4 * D];
    int tid = threadIdx.x; // 256 threads
    for (int i = tid; i < B * D; i += blockDim.x) {
        int b = i / D, j = i % D;
        int hv = head[b];
        conc[b][j]         = ent_emb[hv * D + j];
        conc[b][D + j]     = ent_emb[tail[b] * D + j];
        conc[b][2 * D + j] = (g_tgtStamp[hv] == stampVal) ? g_hid[buf][(long)hv * BD + b * D + j] : 0.f;
        conc[b][3 * D + j] = g_tailHid[b * D + j];
    }
    __syncthreads();
    for (int i = tid; i < B * EVAL_REL; i += blockDim.x) {
        int b = i / EVAL_REL, r = i % EVAL_REL;
        float s = br[r];
        #pragma unroll 4
        for (int k = 0; k < 4 * D; k++) s += conc[b][k] * Wr[k * EVAL_REL + r];
        out[b * EVAL_REL + r] = s;
    }
}

// ---------------- launch ----------------
extern "C" void kernel_launch(void* const* d_in, const int* in_sizes, int n_in,
                              void* d_out, int out_size) {
    (void)in_sizes; (void)n_in; (void)out_size;
    const int*   head    = (const int*)d_in[0];
    const int*   tail    = (const int*)d_in[1];
    const int*   eh      = (const int*)d_in[2];
    const int*   et      = (const int*)d_in[3];
    const int*   er      = (const int*)d_in[4];
    const float* ew      = (const float*)d_in[5];
    const float* ent_emb = (const float*)d_in[6];
    const float* rel_embs= (const float*)d_in[7];
    const float* Wlin    = (const float*)d_in[8];
    const float* blin    = (const float*)d_in[9];
    const float* Wrel    = (const float*)d_in[10];
    const float* brel    = (const float*)d_in[11];
    const float* Watt    = (const float*)d_in[12];
    const float* batt    = (const float*)d_in[13];
    const float* Wr      = (const float*)d_in[14];
    const float* br      = (const float*)d_in[15];
    float* out = (float*)d_out;

    const int EB = (E_EDGES + 255) / 256;

    k_clear<<<120, 256>>>();
    k_relw<<<1, 256>>>(head, tail, ent_emb, Wrel, brel, Watt, batt);

    // ---- pass 0: head -> tail ----
    k_init<<<1, 512>>>(head, ent_emb, 0, /*srcStamp=*/1);
    // layer 0: src=A(stamp1) -> dst=B (tgtStamp1, counters step0)
    k_build  <<<EB, 256>>>(eh, et, 1, 1, 0, 1);
    k_scatter<<<120, 256>>>(eh, et, er, ew, rel_embs, /*l=*/0, 0, 0, 1);
    k_linear <<<60, 256>>>(Wlin, blin, 0, 0, 1, /*nextSrc=*/2);
    // layer 1: src=B(stamp2) -> dst=A (tgtStamp2, counters step1)
    k_build  <<<EB, 256>>>(eh, et, 2, 2, 1, 0);
    k_scatter<<<120, 256>>>(eh, et, er, ew, rel_embs, /*l=*/1, 1, 1, 0);
    k_linear <<<60, 256>>>(Wlin, blin, 1, 1, 0, /*nextSrc=*/0);
    k_extract_tail<<<1, 512>>>(tail, 0, /*stamp=*/2);

    // ---- pass 1: tail -> head ----
    k_init<<<1, 512>>>(tail, ent_emb, 0, /*srcStamp=*/3);
    // layer 0: src=A(stamp3) -> dst=B (tgtStamp3, counters step2)
    k_build  <<<EB, 256>>>(eh, et, 3, 3, 2, 1);
    k_scatter<<<120, 256>>>(eh, et, er, ew, rel_embs, /*l=*/0, 2, 0, 1);
    k_linear <<<60, 256>>>(Wlin, blin, 0, 2, 1, /*nextSrc=*/4);
    // layer 1: src=B(stamp4) -> dst=A (tgtStamp4, counters step3)
    k_build  <<<EB, 256>>>(eh, et, 4, 4, 3, 0);
    k_scatter<<<120, 256>>>(eh, et, er, ew, rel_embs, /*l=*/1, 3, 1, 0);
    k_linear <<<60, 256>>>(Wlin, blin, 1, 3, 0, /*nextSrc=*/0);

    k_final<<<1, 256>>>(head, tail, ent_emb, Wr, br, out, 0, /*stamp=*/4);
}

// round 5
// speedup vs baseline: 1.6654x; 1.6654x over previous
#include <cuda_runtime.h>
#include <math.h>

#define N_ENT 30000
#define ALL_REL 221
#define D 32
#define NL 2
#define EVAL_REL 86
#define B 16
#define E_EDGES 120000
#define BD (B * D) /* 512 */
#define NBLK 128
#define NTHR 256

// ---------------- device scratch (no allocations allowed) ----------------
// hid buffers: pass0 ping-pongs 0<->1, pass1 ping-pongs 2<->3
__device__ float g_hid[4][N_ENT * BD];
__device__ int   g_sStamp[N_ENT];     // promoted-source bits: bit0=pass0(L1 src), bit1=pass1(L1 src)
__device__ int   g_tStamp[N_ENT];     // target-touched bits: 1=p0L0, 2=p0L1, 4=p1L0, 8=p1L1
__device__ int   g_eList0[E_EDGES];   // active edges, pass0 (reused across layers)
__device__ int   g_eList1[E_EDGES];   // active edges, pass1
__device__ int   g_tList0[N_ENT];     // touched targets, pass0
__device__ int   g_tList1[N_ENT];     // touched targets, pass1
__device__ int   g_cnt[8];            // [4l+0]=e p0, [4l+1]=e p1, [4l+2]=t p0, [4l+3]=t p1
__device__ float g_relw[NL * B * ALL_REL];

// software grid barrier state
__device__ unsigned g_barCount = 0;
__device__ volatile unsigned g_barGen = 0;

__device__ __forceinline__ void gridBarrier() {
    __threadfence();          // release: order my writes to device scope
    __syncthreads();
    if (threadIdx.x == 0) {
        unsigned gen = g_barGen;
        if (atomicAdd(&g_barCount, 1u) == (unsigned)(NBLK - 1)) {
            g_barCount = 0;
            __threadfence();
            g_barGen = gen + 1u;
        } else {
            while (g_barGen == gen) { __nanosleep(64); }
        }
    }
    __syncthreads();
    __threadfence();          // acquire: fence.gpu -> CCTL.IVALL flushes L1D, fresh reads
}

__global__ void __launch_bounds__(NTHR, 1)
emer_persist(const int* __restrict__ head, const int* __restrict__ tail,
             const int* __restrict__ eh, const int* __restrict__ et,
             const int* __restrict__ er, const float* __restrict__ ew,
             const float* __restrict__ ent_emb, const float* __restrict__ rel_embs,
             const float* __restrict__ Wlin, const float* __restrict__ blin,
             const float* __restrict__ Wrel, const float* __restrict__ brel,
             const float* __restrict__ Watt, const float* __restrict__ batt,
             const float* __restrict__ Wr, const float* __restrict__ br,
             float* __restrict__ out) {
    const int tid  = threadIdx.x;
    const int bid  = blockIdx.x;
    const int gtid = bid * NTHR + tid;
    const int nth  = NBLK * NTHR;
    const int lane = tid & 31;
    const int wib  = tid >> 5;            // warp in block
    const int gw   = gtid >> 5;           // global warp
    const int nw   = nth >> 5;

    __shared__ float sRow[8][BD];         // 16 KB (linear staging)
    __shared__ float sW[D * D];           // 4 KB
    __shared__ float sb[D];
    __shared__ float sRelw[B * ALL_REL];  // ~14 KB (scatter relw slice)
    __shared__ float sHt[B * 2 * D];      // 4 KB (relw input)
    __shared__ float sH5[B * 5];
    __shared__ int   sHead[B], sTail[B];
    __shared__ float sConc[B][4 * D];     // 8 KB (final)

    // ===================== Phase 0: clears + relw + init =====================
    if (bid == 0) {
        // relation attention weights, both layers
        for (int idx = tid; idx < B * 2 * D; idx += NTHR) {
            int b = idx / (2 * D), j = idx % (2 * D);
            int ent = (j < D) ? head[b] : tail[b];
            int jj  = (j < D) ? j : j - D;
            sHt[b * 2 * D + j] = ent_emb[ent * D + jj];
        }
        __syncthreads();
        for (int l = 0; l < NL; l++) {
            for (int idx = tid; idx < B * 5; idx += NTHR) {
                int b = idx / 5, k = idx % 5;
                float s = brel[l * 5 + k];
                #pragma unroll 8
                for (int j = 0; j < 2 * D; j++)
                    s += sHt[b * 2 * D + j] * Wrel[l * (2 * D * 5) + j * 5 + k];
                sH5[b * 5 + k] = fmaxf(s, 0.f);
            }
            __syncthreads();
            for (int idx = tid; idx < B * ALL_REL; idx += NTHR) {
                int b = idx / ALL_REL, r = idx % ALL_REL;
                float s = batt[l * ALL_REL + r];
                #pragma unroll
                for (int k = 0; k < 5; k++)
                    s += sH5[b * 5 + k] * Watt[l * (5 * ALL_REL) + k * ALL_REL + r];
                g_relw[l * B * ALL_REL + b * ALL_REL + r] = 1.f / (1.f + expf(-s));
            }
            __syncthreads();
        }
    } else if (bid == 1 || bid == 2) {
        // init rows for pass (bid-1): zero the B init rows, then set diagonal
        int pass = bid - 1;
        const int* idxs = pass ? tail : head;
        float* hid = g_hid[pass * 2];     // pass0 -> buf0, pass1 -> buf2
        for (int i = tid; i < B * BD; i += NTHR)
            hid[(long)idxs[i / BD] * BD + (i % BD)] = 0.f;
        __syncthreads();
        for (int i = tid; i < B * D; i += NTHR) {
            int b = i / D, j = i % D;
            hid[(long)idxs[b] * BD + b * D + j] = ent_emb[idxs[b] * D + j];
        }
    } else {
        // clear stamps + counters
        int base = (bid - 3) * NTHR + tid;
        int stride = (NBLK - 3) * NTHR;
        for (int i = base; i < N_ENT; i += stride) { g_sStamp[i] = 0; g_tStamp[i] = 0; }
        if (bid == 3 && tid < 8) g_cnt[tid] = 0;
    }
    gridBarrier();

    // ===================== layer loop =====================
    for (int l = 0; l < NL; l++) {
        const float* src0 = g_hid[l == 0 ? 0 : 1];
        float*       dst0 = g_hid[l == 0 ? 1 : 0];
        const float* src1 = g_hid[l == 0 ? 2 : 3];
        float*       dst1 = g_hid[l == 0 ? 3 : 2];
        const int bit0 = (l == 0) ? 1 : 2;   // tStamp bits pass0
        const int bit1 = (l == 0) ? 4 : 8;   // tStamp bits pass1

        // ---- scan: compact active edges, first-touch-zero targets (both passes) ----
        if (tid < B) { sHead[tid] = head[tid]; sTail[tid] = tail[tid]; }
        __syncthreads();
        for (int i = gtid; i < E_EDGES; i += nth) {
            int h = eh[i];
            bool a0, a1;
            if (l == 0) {
                a0 = false; a1 = false;
                #pragma unroll
                for (int b = 0; b < B; b++) { a0 |= (h == sHead[b]); a1 |= (h == sTail[b]); }
            } else {
                int st = g_sStamp[h];
                a0 = (st & 1); a1 = (st & 2);
            }
            if (a0 | a1) {
                int tv = et[i];
                if (a0) {
                    int p = atomicAdd(&g_cnt[4 * l + 0], 1); g_eList0[p] = i;
                    int old = atomicOr(&g_tStamp[tv], bit0);
                    if (!(old & bit0)) {
                        int q = atomicAdd(&g_cnt[4 * l + 2], 1); g_tList0[q] = tv;
                        float4* row = (float4*)(dst0 + (long)tv * BD);
                        #pragma unroll 8
                        for (int j = 0; j < BD / 4; j++) row[j] = make_float4(0.f, 0.f, 0.f, 0.f);
                    }
                }
                if (a1) {
                    int p = atomicAdd(&g_cnt[4 * l + 1], 1); g_eList1[p] = i;
                    int old = atomicOr(&g_tStamp[tv], bit1);
                    if (!(old & bit1)) {
                        int q = atomicAdd(&g_cnt[4 * l + 3], 1); g_tList1[q] = tv;
                        float4* row = (float4*)(dst1 + (long)tv * BD);
                        #pragma unroll 8
                        for (int j = 0; j < BD / 4; j++) row[j] = make_float4(0.f, 0.f, 0.f, 0.f);
                    }
                }
            }
        }
        gridBarrier();

        // ---- scatter: one warp per active edge, both passes fused ----
        {
            for (int i = tid; i < B * ALL_REL; i += NTHR)
                sRelw[i] = g_relw[l * B * ALL_REL + i];
            __syncthreads();
            int n0 = *(volatile int*)&g_cnt[4 * l + 0];
            int n1 = *(volatile int*)&g_cnt[4 * l + 1];
            const float* relL = rel_embs + l * ALL_REL * D;
            int tot = n0 + n1;
            for (int w = gw; w < tot; w += nw) {
                int e; const float* src; float* dst;
                if (w < n0) { e = g_eList0[w];      src = src0; dst = dst0; }
                else        { e = g_eList1[w - n0]; src = src1; dst = dst1; }
                int h = eh[e], tv = et[e], r = er[e];
                float relv = relL[r * D + lane] * ew[e];
                const float* srow = src + (long)h * BD;
                float* drow = dst + (long)tv * BD;
                #pragma unroll
                for (int b = 0; b < B; b++) {
                    float rw = sRelw[b * ALL_REL + r];
                    atomicAdd(&drow[b * D + lane], rw * relv * srow[b * D + lane]);
                }
            }
        }
        gridBarrier();

        // ---- linear: one warp per touched entity, in-place relu(row @ Wlin + b) ----
        {
            for (int i = tid; i < D * D; i += NTHR) sW[i] = Wlin[l * D * D + i];
            if (tid < D) sb[tid] = blin[l * D + tid];
            __syncthreads();
            int t0 = *(volatile int*)&g_cnt[4 * l + 2];
            int t1 = *(volatile int*)&g_cnt[4 * l + 3];
            int tot = t0 + t1;
            for (int w = gw; w < tot; w += nw) {
                int v; float* buf; int pbit;
                if (w < t0) { v = g_tList0[w];      buf = dst0; pbit = 1; }
                else        { v = g_tList1[w - t0]; buf = dst1; pbit = 2; }
                float* row = buf + (long)v * BD;
                for (int i = lane; i < BD; i += 32) sRow[wib][i] = row[i];
                __syncwarp();
                float outv[B];
                #pragma unroll
                for (int b = 0; b < B; b++) {
                    float s = sb[lane];
                    #pragma unroll
                    for (int ji = 0; ji < D; ji++)
                        s += sRow[wib][b * D + ji] * sW[ji * D + lane];
                    outv[b] = fmaxf(s, 0.f);
                }
                __syncwarp();
                #pragma unroll
                for (int b = 0; b < B; b++) row[b * D + lane] = outv[b];
                if (lane == 0 && l == 0) atomicOr(&g_sStamp[v], pbit);
            }
        }
        gridBarrier();
    }

    // ===================== final readout (block 0) =====================
    if (bid == 0) {
        for (int i = tid; i < B * D; i += NTHR) {
            int b = i / D, j = i % D;
            int hv = head[b], tv = tail[b];
            sConc[b][j]         = ent_emb[hv * D + j];
            sConc[b][D + j]     = ent_emb[tv * D + j];
            // head_hid: pass1 (tail->head) result at head, lives in buf2, valid if p1L1 touched
            sConc[b][2 * D + j] = (g_tStamp[hv] & 8) ? g_hid[2][(long)hv * BD + b * D + j] : 0.f;
            // tail_hid: pass0 (head->tail) result at tail, lives in buf0, valid if p0L1 touched
            sConc[b][3 * D + j] = (g_tStamp[tv] & 2) ? g_hid[0][(long)tv * BD + b * D + j] : 0.f;
        }
        __syncthreads();
        for (int i = tid; i < B * EVAL_REL; i += NTHR) {
            int b = i / EVAL_REL, r = i % EVAL_REL;
            float s = br[r];
            #pragma unroll 4
            for (int k = 0; k < 4 * D; k++) s += sConc[b][k] * Wr[k * EVAL_REL + r];
            out[b * EVAL_REL + r] = s;
        }
    }
}

// ---------------- launch ----------------
extern "C" void kernel_launch(void* const* d_in, const int* in_sizes, int n_in,
                              void* d_out, int out_size) {
    (void)in_sizes; (void)n_in; (void)out_size;
    const int*   head    = (const int*)d_in[0];
    const int*   tail    = (const int*)d_in[1];
    const int*   eh      = (const int*)d_in[2];
    const int*   et      = (const int*)d_in[3];
    const int*   er      = (const int*)d_in[4];
    const float* ew      = (const float*)d_in[5];
    const float* ent_emb = (const float*)d_in[6];
    const float* rel_embs= (const float*)d_in[7];
    const float* Wlin    = (const float*)d_in[8];
    const float* blin    = (const float*)d_in[9];
    const float* Wrel    = (const float*)d_in[10];
    const float* brel    = (const float*)d_in[11];
    const float* Watt    = (const float*)d_in[12];
    const float* batt    = (const float*)d_in[13];
    const float* Wr      = (const float*)d_in[14];
    const float* br      = (const float*)d_in[15];
    float* out = (float*)d_out;

    emer_persist<<<NBLK, NTHR>>>(head, tail, eh, et, er, ew, ent_emb, rel_embs,
                                 Wlin, blin, Wrel, brel, Watt, batt, Wr, br, out);
}